// round 4
// baseline (speedup 1.0000x reference)
#include <cuda_runtime.h>
#include <cuda_bf16.h>
#include <cstdint>

// Idx2PixelLayer — R3: bin points by table row (i0), then gather bin-by-bin so
// table reads become a near-sequential stream with L2-resident working window.
//
// K0: zero per-bin counters
// K1: compute (i0,i1,d0,d1) per point, pack 8B record, atomic scatter into bin
// K2: one block per bin; gather + bilerp + scatter result to out[orig_id]
//
// Record (uint2): .x = (q0<<16)|q1  with q = floor(d*65536)  (16-bit fixed pt)
//                 .y = (orig_id<<11)|i1                      (20b id, 11b i1)

static constexpr int   HW    = 2048;
static constexpr int   CH    = 8;
static constexpr float MODV  = 2044.0f;   // H - 4
static constexpr int   NBINS = 2046;      // index by i0 directly (i0 in [1,2044])
static constexpr int   CAP   = 736;       // mean 489/bin, ~11 sigma headroom

__device__ uint2 g_recs[NBINS * CAP];     // ~12 MB static scratch
__device__ int   g_cnt[NBINS];

__global__ void k_clear()
{
    int i = blockIdx.x * blockDim.x + threadIdx.x;
    if (i < NBINS) g_cnt[i] = 0;
}

__global__ __launch_bounds__(256)
void k_bin(const float* __restrict__ coords, int n)
{
    int t = blockIdx.x * blockDim.x + threadIdx.x;
    if (t >= n) return;

    float2 co = __ldcs(reinterpret_cast<const float2*>(coords) + t);

    // floor-mod (python semantics) then +1 ; result in [1, 2045)
    float c0 = fmodf(co.x - 1.0f, MODV); if (c0 < 0.0f) c0 += MODV; c0 += 1.0f;
    float c1 = fmodf(co.y - 1.0f, MODV); if (c1 < 0.0f) c1 += MODV; c1 += 1.0f;
    // note: c0 <= 2045 < 2048 always, so the reference's zero-mask (c0 > 2048)
    // can never fire; omitted.

    float f0 = floorf(c0), f1 = floorf(c1);
    float d0 = c0 - f0,   d1 = c1 - f1;         // in [0,1)
    int i0 = (int)f0, i1 = (int)f1;             // in [1,2044]

    unsigned q0 = (unsigned)(d0 * 65536.0f);    // 0..65535
    unsigned q1 = (unsigned)(d1 * 65536.0f);

    uint2 rec;
    rec.x = (q0 << 16) | q1;
    rec.y = ((unsigned)t << 11) | (unsigned)i1;

    int slot = atomicAdd(&g_cnt[i0], 1);
    if (slot < CAP) g_recs[(size_t)i0 * CAP + slot] = rec;
}

__global__ __launch_bounds__(256)
void k_gather(const float* __restrict__ visible, float* __restrict__ out)
{
    int bin = blockIdx.x;                 // == i0
    int cnt = g_cnt[bin];
    if (cnt > CAP) cnt = CAP;

    for (int slot = threadIdx.x; slot < cnt; slot += 256) {
        uint2 rec = g_recs[(size_t)bin * CAP + slot];
        int i1 = rec.y & 2047;
        int id = rec.y >> 11;
        float d0 = (float)(rec.x >> 16)    * (1.0f / 65536.0f);
        float d1 = (float)(rec.x & 65535u) * (1.0f / 65536.0f);

        // Row bin:   [top_left | bottom_left]  (cols i1, i1+1) 64B contiguous
        // Row bin+1: [top_right | bottom_right]
        const float4* rowA = reinterpret_cast<const float4*>(
            visible + ((size_t)bin * HW + i1) * CH);
        const float4* rowB = rowA + (size_t)HW * CH / 4;

        float4 tl0 = __ldg(rowA + 0), tl1 = __ldg(rowA + 1);
        float4 bl0 = __ldg(rowA + 2), bl1 = __ldg(rowA + 3);
        float4 tr0 = __ldg(rowB + 0), tr1 = __ldg(rowB + 1);
        float4 br0 = __ldg(rowB + 2), br1 = __ldg(rowB + 3);

        float o[8];
        {
            const float* tl = &tl0.x; const float* tr = &tr0.x;
            const float* bl = &bl0.x; const float* br = &br0.x;
            #pragma unroll
            for (int k = 0; k < 4; k++) {
                float mt = tr[k] + d0 * (tl[k] - tr[k]);
                float mb = br[k] + d0 * (bl[k] - br[k]);
                o[k] = mb + d1 * (mt - mb);
            }
            tl = &tl1.x; tr = &tr1.x; bl = &bl1.x; br = &br1.x;
            #pragma unroll
            for (int k = 0; k < 4; k++) {
                float mt = tr[k] + d0 * (tl[k] - tr[k]);
                float mb = br[k] + d0 * (bl[k] - br[k]);
                o[4 + k] = mb + d1 * (mt - mb);
            }
        }

        // Scatter to original position; default store -> lines assemble in L2.
        float4* dst = reinterpret_cast<float4*>(out + (size_t)id * CH);
        dst[0] = make_float4(o[0], o[1], o[2], o[3]);
        dst[1] = make_float4(o[4], o[5], o[6], o[7]);
    }
}

extern "C" void kernel_launch(void* const* d_in, const int* in_sizes, int n_in,
                              void* d_out, int out_size)
{
    const float* coords  = (const float*)d_in[0];   // (N, 2) float32
    const float* visible = (const float*)d_in[1];   // (2048, 2048, 8) float32
    float* out = (float*)d_out;                     // (N, 8) float32

    int n = in_sizes[0] / 2;

    k_clear<<<(NBINS + 255) / 256, 256>>>();
    k_bin<<<(n + 255) / 256, 256>>>(coords, n);
    k_gather<<<NBINS, 256>>>(visible, out);
}

// round 6
// speedup vs baseline: 2.3592x; 2.3592x over previous
#include <cuda_runtime.h>
#include <cuda_bf16.h>

// Idx2PixelLayer — R4: back to single-kernel gather (R0/R2 architecture),
// 2 points per thread to double per-thread MLP (4 -> 8 independent 32B
// gathers in flight) for better HBM bank-level parallelism.
//  - coords: one float4 __ldcs per thread (both points)
//  - table: ld.global.nc.L2::evict_last.v8.b32 (32B/lane, 4 per point)
//  - out:   four float4 __stcs, 64B contiguous per thread

static constexpr int   HW   = 2048;
static constexpr int   CH   = 8;
static constexpr float MODV = 2044.0f;   // H - 4

struct F8 { float v[8]; };

__device__ __forceinline__ F8 ldg_keep32(const float* p) {
    F8 r;
    asm volatile("ld.global.nc.L2::evict_last.v8.b32 {%0,%1,%2,%3,%4,%5,%6,%7}, [%8];"
                 : "=f"(r.v[0]), "=f"(r.v[1]), "=f"(r.v[2]), "=f"(r.v[3]),
                   "=f"(r.v[4]), "=f"(r.v[5]), "=f"(r.v[6]), "=f"(r.v[7])
                 : "l"(p));
    return r;
}

__device__ __forceinline__ void addr_and_w(float cx, float cy,
                                           const float* visible,
                                           const float*& rowA, const float*& rowB,
                                           float& d0, float& d1)
{
    float c0 = fmodf(cx - 1.0f, MODV); if (c0 < 0.0f) c0 += MODV; c0 += 1.0f;
    float c1 = fmodf(cy - 1.0f, MODV); if (c1 < 0.0f) c1 += MODV; c1 += 1.0f;
    // c in [1, 2045) < 2048, so the reference's zero-mask (c0 > 2048) never
    // fires; omitted.
    float f0 = floorf(c0), f1 = floorf(c1);
    d0 = c0 - f0; d1 = c1 - f1;
    int i0 = (int)f0, i1 = (int)f1;
    rowA = visible + ((size_t)i0 * HW + i1) * CH;   // [tl | bl], 64B
    rowB = rowA + (size_t)HW * CH;                  // [tr | br], 64B
}

__device__ __forceinline__ void bilerp8(const F8& tl8, const F8& bl8,
                                        const F8& tr8, const F8& br8,
                                        float d0, float d1, float* o)
{
    #pragma unroll
    for (int k = 0; k < 8; k++) {
        float mt = tr8.v[k] + d0 * (tl8.v[k] - tr8.v[k]);
        float mb = br8.v[k] + d0 * (bl8.v[k] - br8.v[k]);
        o[k] = mb + d1 * (mt - mb);
    }
}

__global__ __launch_bounds__(256)
void idx2pixel_kernel(const float* __restrict__ coords,
                      const float* __restrict__ visible,
                      float* __restrict__ out,
                      int n)  // n = number of POINT PAIRS
{
    int t = blockIdx.x * blockDim.x + threadIdx.x;
    if (t >= n) return;

    // two points per thread: 2t, 2t+1
    float4 co = __ldcs(reinterpret_cast<const float4*>(coords) + t);

    const float *a0, *b0, *a1, *b1;
    float d0A, d1A, d0B, d1B;
    addr_and_w(co.x, co.y, visible, a0, b0, d0A, d1A);
    addr_and_w(co.z, co.w, visible, a1, b1, d0B, d1B);

    // Issue all 8 gathers before any compute (max MLP).
    F8 tlA = ldg_keep32(a0);     F8 blA = ldg_keep32(a0 + 8);
    F8 trA = ldg_keep32(b0);     F8 brA = ldg_keep32(b0 + 8);
    F8 tlB = ldg_keep32(a1);     F8 blB = ldg_keep32(a1 + 8);
    F8 trB = ldg_keep32(b1);     F8 brB = ldg_keep32(b1 + 8);

    float oA[8], oB[8];
    bilerp8(tlA, blA, trA, brA, d0A, d1A, oA);
    bilerp8(tlB, blB, trB, brB, d0B, d1B, oB);

    float4* dst = reinterpret_cast<float4*>(out + (size_t)t * 2 * CH);
    __stcs(dst + 0, make_float4(oA[0], oA[1], oA[2], oA[3]));
    __stcs(dst + 1, make_float4(oA[4], oA[5], oA[6], oA[7]));
    __stcs(dst + 2, make_float4(oB[0], oB[1], oB[2], oB[3]));
    __stcs(dst + 3, make_float4(oB[4], oB[5], oB[6], oB[7]));
}

// Tail kernel for odd N (not hit here: N = 1e6 is even, but stay correct).
__global__ void idx2pixel_tail(const float* __restrict__ coords,
                               const float* __restrict__ visible,
                               float* __restrict__ out,
                               int start, int n)
{
    int t = start + blockIdx.x * blockDim.x + threadIdx.x;
    if (t >= n) return;
    float2 co = reinterpret_cast<const float2*>(coords)[t];
    const float *ra, *rb; float d0, d1;
    addr_and_w(co.x, co.y, visible, ra, rb, d0, d1);
    F8 tl = ldg_keep32(ra), bl = ldg_keep32(ra + 8);
    F8 tr = ldg_keep32(rb), br = ldg_keep32(rb + 8);
    float o[8];
    bilerp8(tl, bl, tr, br, d0, d1, o);
    float4* dst = reinterpret_cast<float4*>(out + (size_t)t * CH);
    dst[0] = make_float4(o[0], o[1], o[2], o[3]);
    dst[1] = make_float4(o[4], o[5], o[6], o[7]);
}

extern "C" void kernel_launch(void* const* d_in, const int* in_sizes, int n_in,
                              void* d_out, int out_size)
{
    const float* coords  = (const float*)d_in[0];   // (N, 2) float32
    const float* visible = (const float*)d_in[1];   // (2048, 2048, 8) float32
    float* out = (float*)d_out;                     // (N, 8) float32

    int n = in_sizes[0] / 2;       // number of points
    int pairs = n / 2;
    int threads = 256;
    if (pairs > 0) {
        int blocks = (pairs + threads - 1) / threads;
        idx2pixel_kernel<<<blocks, threads>>>(coords, visible, out, pairs);
    }
    if (n & 1) {
        idx2pixel_tail<<<1, 1>>>(coords, visible, out, n - 1, n);
    }
}